// round 5
// baseline (speedup 1.0000x reference)
#include <cuda_runtime.h>
#include <math.h>
#include <stdint.h>

#define BB   4
#define SS   1024
#define HH   16
#define SZ   64
#define DIMM 1024
#define NINF -10000.0f

// ---------------- scratch (device globals; no runtime allocation) ----------
__device__ float g_q[BB * SS * DIMM];
__device__ float g_k[BB * SS * DIMM];
__device__ float g_v[BB * SS * DIMM];
__device__ float g_ctx[BB * SS * DIMM];
__device__ float g_res[BB * SS * DIMM];
__device__ float g_xr[BB * SS * DIMM];        // tf32-rounded x
__device__ float g_wr[4][DIMM * DIMM];        // tf32-rounded Wq,Wk,Wv,Wo
__device__ float g_rowm[BB * HH * SS];        // per-row max
__device__ float g_rowl[BB * HH * SS];        // per-row 1/sum
__device__ float g_attn_scratch[BB * HH * SS * SS];

// ---------------- small PTX helpers ----------------------------------------
__device__ __forceinline__ uint32_t f2tf(float f) {
    uint32_t r;
    asm volatile("cvt.rna.tf32.f32 %0, %1;" : "=r"(r) : "f"(f));
    return r;
}
__device__ __forceinline__ float tf32r(float f) { return __uint_as_float(f2tf(f)); }

__device__ __forceinline__ void mma_tf32(float c[4], const uint32_t a[4],
                                         const uint32_t b[2]) {
    asm volatile(
        "mma.sync.aligned.m16n8k8.row.col.f32.tf32.tf32.f32 "
        "{%0,%1,%2,%3}, {%4,%5,%6,%7}, {%8,%9}, {%0,%1,%2,%3};"
        : "+f"(c[0]), "+f"(c[1]), "+f"(c[2]), "+f"(c[3])
        : "r"(a[0]), "r"(a[1]), "r"(a[2]), "r"(a[3]), "r"(b[0]), "r"(b[1]));
}
__device__ __forceinline__ void cp16(uint32_t s, const void* g) {
    asm volatile("cp.async.cg.shared.global [%0], [%1], 16;" :: "r"(s), "l"(g));
}
#define CP_COMMIT() asm volatile("cp.async.commit_group;")
#define CP_WAIT1()  asm volatile("cp.async.wait_group 1;")
#define CP_WAIT0()  asm volatile("cp.async.wait_group 0;")

// ---------------------------------------------------------------------------
// preround: tf32-round x and the four weight matrices (once)
// grid (1024, 5), 256 threads
// ---------------------------------------------------------------------------
__global__ __launch_bounds__(256) void preround_kernel(
    const float* __restrict__ x, float* __restrict__ xr,
    const float* __restrict__ Wq, const float* __restrict__ Wk,
    const float* __restrict__ Wv, const float* __restrict__ Wo,
    float* __restrict__ wr)
{
    const int y = blockIdx.y;
    const float* in;
    float* out;
    int n4;
    if (y == 0) { in = x;  out = xr;                n4 = BB * SS * DIMM / 4; }
    else {
        in = (y == 1) ? Wq : (y == 2) ? Wk : (y == 3) ? Wv : Wo;
        out = wr + (size_t)(y - 1) * DIMM * DIMM;   n4 = DIMM * DIMM / 4;
    }
    for (int i = blockIdx.x * 256 + threadIdx.x; i < n4; i += 1024 * 256) {
        float4 v = ((const float4*)in)[i];
        v.x = tf32r(v.x); v.y = tf32r(v.y); v.z = tf32r(v.z); v.w = tf32r(v.w);
        ((float4*)out)[i] = v;
    }
}

// ---------------------------------------------------------------------------
// TF32 GEMM core (operands PRE-ROUNDED): 128x128x32 tiles, 256 thr, 8 warps
// ---------------------------------------------------------------------------
#define A_STR 36
#define W_STR 136
#define A_TILE (128 * A_STR)
#define W_TILE (32 * W_STR)
#define GEMM_SMEM ((A_TILE + W_TILE) * 2 * 4)  // 71680 B

struct GemmCore {
    const float* A; const float* W; int N; int K; int bm; int bn;
    float* smem;
    float acc[4][4][4];

    __device__ __forceinline__ void run(int tid) {
        float* As[2] = { smem, smem + A_TILE + W_TILE };
        float* Ws[2] = { smem + A_TILE, smem + A_TILE + W_TILE + A_TILE };
        const int lane = tid & 31, warp = tid >> 5;
        const int wm = warp >> 2, wn = warp & 3;
        const int r = lane >> 2, cl = lane & 3;

#pragma unroll
        for (int mt = 0; mt < 4; mt++)
#pragma unroll
            for (int nt = 0; nt < 4; nt++)
#pragma unroll
                for (int i = 0; i < 4; i++) acc[mt][nt][i] = 0.f;

        auto load_stage = [&](int b, int kt) {
            float* as = As[b];
            float* ws = Ws[b];
#pragma unroll
            for (int j = 0; j < 4; j++) {
                const int idx = tid + j * 256;
                const int ar = idx >> 3, ac = (idx & 7) * 4;
                cp16((uint32_t)__cvta_generic_to_shared(as + ar * A_STR + ac),
                     A + (size_t)(bm + ar) * K + kt + ac);
                const int wk = idx >> 5, wc = (idx & 31) * 4;
                cp16((uint32_t)__cvta_generic_to_shared(ws + wk * W_STR + wc),
                     W + (size_t)(kt + wk) * N + bn + wc);
            }
        };

        load_stage(0, 0);
        CP_COMMIT();

        const int T = K / 32;
        int buf = 0;
        for (int t = 0; t < T; t++) {
            if (t + 1 < T) { load_stage(buf ^ 1, (t + 1) * 32); CP_COMMIT(); CP_WAIT1(); }
            else           { CP_WAIT0(); }
            __syncthreads();
            const float* as = As[buf];
            const float* ws = Ws[buf];
#pragma unroll
            for (int ks = 0; ks < 4; ks++) {
                uint32_t af[4][4];
#pragma unroll
                for (int mt = 0; mt < 4; mt++) {
                    const float* p = as + (wm * 64 + mt * 16 + r) * A_STR + ks * 8 + cl;
                    af[mt][0] = __float_as_uint(p[0]);
                    af[mt][1] = __float_as_uint(p[8 * A_STR]);
                    af[mt][2] = __float_as_uint(p[4]);
                    af[mt][3] = __float_as_uint(p[8 * A_STR + 4]);
                }
                uint32_t bf[4][2];
#pragma unroll
                for (int nt = 0; nt < 4; nt++) {
                    const float* p = ws + (ks * 8 + cl) * W_STR + wn * 32 + nt * 8 + r;
                    bf[nt][0] = __float_as_uint(p[0]);
                    bf[nt][1] = __float_as_uint(p[4 * W_STR]);
                }
#pragma unroll
                for (int mt = 0; mt < 4; mt++)
#pragma unroll
                    for (int nt = 0; nt < 4; nt++)
                        mma_tf32(acc[mt][nt], af[mt], bf[nt]);
            }
            __syncthreads();
            buf ^= 1;
        }
    }
};

// QKV: outputs tf32-rounded q/k/v (identical to rounding at consumer side)
__global__ __launch_bounds__(256, 2) void qkv_gemm(
    const float* __restrict__ xr, const float* __restrict__ wr,
    const float* __restrict__ bq, float* __restrict__ qo,
    const float* __restrict__ bk, float* __restrict__ ko,
    const float* __restrict__ bv, float* __restrict__ vo)
{
    extern __shared__ float sm[];
    const float* W = wr + (size_t)blockIdx.z * DIMM * DIMM;
    const float* bias = (blockIdx.z == 0) ? bq : (blockIdx.z == 1) ? bk : bv;
    float* C = (blockIdx.z == 0) ? qo : (blockIdx.z == 1) ? ko : vo;

    GemmCore g;
    g.A = xr; g.W = W; g.N = DIMM; g.K = DIMM;
    g.bm = blockIdx.y * 128; g.bn = blockIdx.x * 128; g.smem = sm;
    g.run(threadIdx.x);

    const int lane = threadIdx.x & 31, warp = threadIdx.x >> 5;
    const int wm = warp >> 2, wn = warp & 3;
    const int r = lane >> 2, cl = lane & 3;
#pragma unroll
    for (int mt = 0; mt < 4; mt++) {
        const int row0 = g.bm + wm * 64 + mt * 16 + r;
#pragma unroll
        for (int nt = 0; nt < 4; nt++) {
            const int col = g.bn + wn * 32 + nt * 8 + 2 * cl;
            const float b0 = bias[col], b1 = bias[col + 1];
            *(float2*)(C + (size_t)row0 * DIMM + col) =
                make_float2(tf32r(g.acc[mt][nt][0] + b0), tf32r(g.acc[mt][nt][1] + b1));
            *(float2*)(C + (size_t)(row0 + 8) * DIMM + col) =
                make_float2(tf32r(g.acc[mt][nt][2] + b0), tf32r(g.acc[mt][nt][3] + b1));
        }
    }
}

// O projection with residual (residual = ORIGINAL x; output full f32 for LN)
__global__ __launch_bounds__(256, 2) void o_gemm(
    const float* __restrict__ A, const float* __restrict__ W,
    const float* __restrict__ bias, const float* __restrict__ resid,
    float* __restrict__ C)
{
    extern __shared__ float sm[];
    GemmCore g;
    g.A = A; g.W = W; g.N = DIMM; g.K = DIMM;
    g.bm = blockIdx.y * 128; g.bn = blockIdx.x * 128; g.smem = sm;
    g.run(threadIdx.x);

    const int lane = threadIdx.x & 31, warp = threadIdx.x >> 5;
    const int wm = warp >> 2, wn = warp & 3;
    const int r = lane >> 2, cl = lane & 3;
#pragma unroll
    for (int mt = 0; mt < 4; mt++) {
        const int row0 = g.bm + wm * 64 + mt * 16 + r;
#pragma unroll
        for (int nt = 0; nt < 4; nt++) {
            const int col = g.bn + wn * 32 + nt * 8 + 2 * cl;
            const float b0 = bias[col], b1 = bias[col + 1];
            float v00 = g.acc[mt][nt][0] + b0 + resid[(size_t)row0 * DIMM + col];
            float v01 = g.acc[mt][nt][1] + b1 + resid[(size_t)row0 * DIMM + col + 1];
            float v10 = g.acc[mt][nt][2] + b0 + resid[(size_t)(row0 + 8) * DIMM + col];
            float v11 = g.acc[mt][nt][3] + b1 + resid[(size_t)(row0 + 8) * DIMM + col + 1];
            *(float2*)(C + (size_t)row0 * DIMM + col)       = make_float2(v00, v01);
            *(float2*)(C + (size_t)(row0 + 8) * DIMM + col) = make_float2(v10, v11);
        }
    }
}

// ---------------------------------------------------------------------------
// scores_kernel: writes RAW s = Q.K^T/8 + rel + mask*NINF.
// 128x128 tile, K=64 single shot. grid (8 t, 8 s, 64 bh)
// ---------------------------------------------------------------------------
#define SC_STR 68
#define SC_SMEM (2 * 128 * SC_STR * 4)   // 69632 B

__global__ __launch_bounds__(256, 2) void scores_kernel(
    const float* __restrict__ q, const float* __restrict__ k,
    const float* __restrict__ rel, const int* __restrict__ mask,
    float* __restrict__ sraw)
{
    extern __shared__ float sm[];
    float* sQ = sm;
    float* sK = sm + 128 * SC_STR;

    const int tid = threadIdx.x;
    const int lane = tid & 31, warp = tid >> 5;
    const int wm = warp >> 2, wn = warp & 3;
    const int r = lane >> 2, cl = lane & 3;

    const int bh = blockIdx.z;
    const int b = bh >> 4, h = bh & 15;
    const int s0 = blockIdx.y * 128;
    const int t0 = blockIdx.x * 128;

    const float* qb = q + ((size_t)b * SS + s0) * DIMM + h * SZ;
    const float* kb = k + ((size_t)b * SS + t0) * DIMM + h * SZ;
    const float* relb = rel + ((size_t)h * SS + s0) * SS + t0;
    const int* maskb = mask + b * SS + t0;

    for (int idx = tid; idx < 128 * 16; idx += 256) {
        const int rr = idx >> 4, c4 = (idx & 15) * 4;
        float4 qv = *(const float4*)(qb + (size_t)rr * DIMM + c4);
        qv.x *= 0.125f; qv.y *= 0.125f; qv.z *= 0.125f; qv.w *= 0.125f;
        *(float4*)&sQ[rr * SC_STR + c4] = qv;
        *(float4*)&sK[rr * SC_STR + c4] = *(const float4*)(kb + (size_t)rr * DIMM + c4);
    }
    __syncthreads();

    float acc[4][4][4];
#pragma unroll
    for (int mt = 0; mt < 4; mt++)
#pragma unroll
        for (int nt = 0; nt < 4; nt++)
#pragma unroll
            for (int i = 0; i < 4; i++) acc[mt][nt][i] = 0.f;

#pragma unroll
    for (int ks = 0; ks < 8; ks++) {
        uint32_t af[4][4];
#pragma unroll
        for (int mt = 0; mt < 4; mt++) {
            const float* p = sQ + (wm * 64 + mt * 16 + r) * SC_STR + ks * 8 + cl;
            af[mt][0] = __float_as_uint(p[0]);
            af[mt][1] = __float_as_uint(p[8 * SC_STR]);
            af[mt][2] = __float_as_uint(p[4]);
            af[mt][3] = __float_as_uint(p[8 * SC_STR + 4]);
        }
        uint32_t bf[4][2];
#pragma unroll
        for (int nt = 0; nt < 4; nt++) {
            const float* p = sK + (wn * 32 + nt * 8 + r) * SC_STR + ks * 8 + cl;
            bf[nt][0] = __float_as_uint(p[0]);
            bf[nt][1] = __float_as_uint(p[4]);
        }
#pragma unroll
        for (int mt = 0; mt < 4; mt++)
#pragma unroll
            for (int nt = 0; nt < 4; nt++)
                mma_tf32(acc[mt][nt], af[mt], bf[nt]);
    }

    float* ob = sraw + (((size_t)bh) * SS + s0) * SS + t0;
#pragma unroll
    for (int mt = 0; mt < 4; mt++) {
        const int row0 = wm * 64 + mt * 16 + r;
#pragma unroll
        for (int nt = 0; nt < 4; nt++) {
            const int col = wn * 32 + nt * 8 + 2 * cl;
            const int2 mk = *(const int2*)(maskb + col);
            const float m0 = (float)mk.x * NINF, m1 = (float)mk.y * NINF;
            const float2 rl0 = *(const float2*)(relb + (size_t)row0 * SS + col);
            const float2 rl1 = *(const float2*)(relb + (size_t)(row0 + 8) * SS + col);
            *(float2*)(ob + (size_t)row0 * SS + col) =
                make_float2(acc[mt][nt][0] + rl0.x + m0, acc[mt][nt][1] + rl0.y + m1);
            *(float2*)(ob + (size_t)(row0 + 8) * SS + col) =
                make_float2(acc[mt][nt][2] + rl1.x + m0, acc[mt][nt][3] + rl1.y + m1);
        }
    }
}

// ---------------------------------------------------------------------------
// stats_kernel: read-only; per row m = max, linv = 1/sum(exp(s-m)).
// grid = BB*HH*SS, 256 threads
// ---------------------------------------------------------------------------
__global__ __launch_bounds__(256) void stats_kernel(
    const float* __restrict__ attn, float* __restrict__ rowm,
    float* __restrict__ rowl)
{
    __shared__ float sred[8];
    const int row = blockIdx.x;
    const int tid = threadIdx.x;

    const float4 sv = ((const float4*)(attn + (size_t)row * SS))[tid];

    float mx = fmaxf(fmaxf(sv.x, sv.y), fmaxf(sv.z, sv.w));
#pragma unroll
    for (int o = 16; o >= 1; o >>= 1) mx = fmaxf(mx, __shfl_xor_sync(~0u, mx, o));
    if ((tid & 31) == 0) sred[tid >> 5] = mx;
    __syncthreads();
    float rowmax = sred[0];
#pragma unroll
    for (int i = 1; i < 8; i++) rowmax = fmaxf(rowmax, sred[i]);

    float s = __expf(sv.x - rowmax) + __expf(sv.y - rowmax) +
              __expf(sv.z - rowmax) + __expf(sv.w - rowmax);
#pragma unroll
    for (int o = 16; o >= 1; o >>= 1) s += __shfl_xor_sync(~0u, s, o);
    __syncthreads();
    if ((tid & 31) == 0) sred[tid >> 5] = s;
    __syncthreads();
    if (tid == 0) {
        float tot = 0.f;
#pragma unroll
        for (int i = 0; i < 8; i++) tot += sred[i];
        rowm[row] = rowmax;
        rowl[row] = 1.f / tot;
    }
}

// ---------------------------------------------------------------------------
// pv_kernel: reads RAW scores, applies p=exp(s-m)*linv in smem, writes the
// normalized attn output AND accumulates ctx = P @ V.
// M-tile 64, K chunks of 64 double-buffered. grid (16 s-tiles, 64 bh).
// ---------------------------------------------------------------------------
#define P_STR 68
#define V_STR 72
#define PV_STAGE (64 * P_STR + 64 * V_STR)     // 8960 floats
#define PV_SMEM ((2 * PV_STAGE + 128) * 4)     // 72192 B

__global__ __launch_bounds__(256, 2) void pv_kernel(
    float* __restrict__ attn, const float* __restrict__ v,
    const float* __restrict__ rowm, const float* __restrict__ rowl,
    float* __restrict__ ctx)
{
    extern __shared__ float sm[];
    float* sP[2] = { sm, sm + PV_STAGE };
    float* sV[2] = { sm + 64 * P_STR, sm + PV_STAGE + 64 * P_STR };
    float* sM = sm + 2 * PV_STAGE;
    float* sL = sM + 64;

    const int tid = threadIdx.x;
    const int lane = tid & 31, warp = tid >> 5;
    const int wm = warp >> 2, wn = warp & 3;   // wm 0..1 (32 rows), wn 0..3 (16 cols)
    const int r = lane >> 2, cl = lane & 3;

    const int bh = blockIdx.y;
    const int b = bh >> 4, h = bh & 15;
    const int s0 = blockIdx.x * 64;

    float* attnb = attn + (((size_t)bh) * SS + s0) * SS;
    const float* vb = v + (size_t)b * SS * DIMM + h * SZ;

    if (tid < 64) {
        sM[tid] = rowm[bh * SS + s0 + tid];
        sL[tid] = rowl[bh * SS + s0 + tid];
    }

    auto load_stage = [&](int buf, int t0) {
#pragma unroll
        for (int j = 0; j < 4; j++) {   // P: 64x16 float4
            const int idx = tid + j * 256;
            const int pr = idx >> 4, c4 = (idx & 15) * 4;
            cp16((uint32_t)__cvta_generic_to_shared(sP[buf] + pr * P_STR + c4),
                 attnb + (size_t)pr * SS + t0 + c4);
        }
#pragma unroll
        for (int j = 0; j < 4; j++) {   // V: 64x16 float4
            const int idx = tid + j * 256;
            const int vr = idx >> 4, c4 = (idx & 15) * 4;
            cp16((uint32_t)__cvta_generic_to_shared(sV[buf] + vr * V_STR + c4),
                 vb + (size_t)(t0 + vr) * DIMM + c4);
        }
    };

    float acc[2][2][4];
#pragma unroll
    for (int mt = 0; mt < 2; mt++)
#pragma unroll
        for (int nt = 0; nt < 2; nt++)
#pragma unroll
            for (int i = 0; i < 4; i++) acc[mt][nt][i] = 0.f;

    load_stage(0, 0);
    CP_COMMIT();

    int buf = 0;
    for (int t = 0; t < 16; t++) {
        if (t + 1 < 16) { load_stage(buf ^ 1, (t + 1) * 64); CP_COMMIT(); CP_WAIT1(); }
        else            { CP_WAIT0(); }
        __syncthreads();

        // transform: p = exp(raw - m) * linv; write attn out; store rounded p
        float* ps = sP[buf];
#pragma unroll
        for (int j = 0; j < 16; j++) {
            const int idx = tid + j * 256;
            const int row = idx >> 6, col = idx & 63;
            const float raw = ps[row * P_STR + col];
            const float p = __expf(raw - sM[row]) * sL[row];
            attnb[(size_t)row * SS + t * 64 + col] = p;
            ps[row * P_STR + col] = tf32r(p);
        }
        __syncthreads();

        const float* vs = sV[buf];
#pragma unroll
        for (int ks = 0; ks < 8; ks++) {
            uint32_t af[2][4];
#pragma unroll
            for (int mt = 0; mt < 2; mt++) {
                const float* p = ps + (wm * 32 + mt * 16 + r) * P_STR + ks * 8 + cl;
                af[mt][0] = __float_as_uint(p[0]);
                af[mt][1] = __float_as_uint(p[8 * P_STR]);
                af[mt][2] = __float_as_uint(p[4]);
                af[mt][3] = __float_as_uint(p[8 * P_STR + 4]);
            }
            uint32_t bf[2][2];
#pragma unroll
            for (int nt = 0; nt < 2; nt++) {
                const float* p = vs + (ks * 8 + cl) * V_STR + wn * 16 + nt * 8 + r;
                bf[nt][0] = __float_as_uint(p[0]);
                bf[nt][1] = __float_as_uint(p[4 * V_STR]);
            }
#pragma unroll
            for (int mt = 0; mt < 2; mt++)
#pragma unroll
                for (int nt = 0; nt < 2; nt++)
                    mma_tf32(acc[mt][nt], af[mt], bf[nt]);
        }
        __syncthreads();
        buf ^= 1;
    }

    // ctx output, tf32-rounded (feeds o_gemm A operand)
#pragma unroll
    for (int mt = 0; mt < 2; mt++) {
        const int row0 = s0 + wm * 32 + mt * 16 + r;
#pragma unroll
        for (int nt = 0; nt < 2; nt++) {
            const int col = h * SZ + wn * 16 + nt * 8 + 2 * cl;
            *(float2*)(ctx + ((size_t)b * SS + row0) * DIMM + col) =
                make_float2(tf32r(acc[mt][nt][0]), tf32r(acc[mt][nt][1]));
            *(float2*)(ctx + ((size_t)b * SS + row0 + 8) * DIMM + col) =
                make_float2(tf32r(acc[mt][nt][2]), tf32r(acc[mt][nt][3]));
        }
    }
}

// ---------------------------------------------------------------------------
// LayerNorm
// ---------------------------------------------------------------------------
__global__ __launch_bounds__(256) void ln_kernel(
    const float* __restrict__ res, const float* __restrict__ gamma,
    const float* __restrict__ beta, float* __restrict__ out)
{
    __shared__ float sred[2][8];
    const int row = blockIdx.x;
    const int tid = threadIdx.x;
    const float4 vv = ((const float4*)(res + (size_t)row * DIMM))[tid];
    float s  = vv.x + vv.y + vv.z + vv.w;
    float ss = vv.x * vv.x + vv.y * vv.y + vv.z * vv.z + vv.w * vv.w;
#pragma unroll
    for (int o = 16; o >= 1; o >>= 1) {
        s  += __shfl_xor_sync(~0u, s, o);
        ss += __shfl_xor_sync(~0u, ss, o);
    }
    if ((tid & 31) == 0) { sred[0][tid >> 5] = s; sred[1][tid >> 5] = ss; }
    __syncthreads();
    float ts = 0.f, tss = 0.f;
#pragma unroll
    for (int i = 0; i < 8; i++) { ts += sred[0][i]; tss += sred[1][i]; }
    const float mu   = ts * (1.f / DIMM);
    const float var  = tss * (1.f / DIMM) - mu * mu;
    const float rstd = rsqrtf(var + 1e-6f);
    const float4 g  = ((const float4*)gamma)[tid];
    const float4 be = ((const float4*)beta)[tid];
    float4 o4;
    o4.x = (vv.x - mu) * rstd * g.x + be.x;
    o4.y = (vv.y - mu) * rstd * g.y + be.y;
    o4.z = (vv.z - mu) * rstd * g.z + be.z;
    o4.w = (vv.w - mu) * rstd * g.w + be.w;
    ((float4*)(out + (size_t)row * DIMM))[tid] = o4;
}

// ---------------------------------------------------------------------------
extern "C" void kernel_launch(void* const* d_in, const int* in_sizes, int n_in,
                              void* d_out, int out_size)
{
    const float* x     = (const float*)d_in[0];
    const int*   mask  = (const int*)d_in[1];
    const float* rel   = (const float*)d_in[2];
    const float* Wq    = (const float*)d_in[3];
    const float* bq    = (const float*)d_in[4];
    const float* Wk    = (const float*)d_in[5];
    const float* bk    = (const float*)d_in[6];
    const float* Wv    = (const float*)d_in[7];
    const float* bv    = (const float*)d_in[8];
    const float* Wo    = (const float*)d_in[9];
    const float* bo    = (const float*)d_in[10];
    const float* gamma = (const float*)d_in[11];
    const float* beta  = (const float*)d_in[12];
    float* out = (float*)d_out;

    float *q, *k, *v, *ctx, *res, *xr, *wr, *rowm, *rowl, *attn_scr;
    cudaGetSymbolAddress((void**)&q,        g_q);
    cudaGetSymbolAddress((void**)&k,        g_k);
    cudaGetSymbolAddress((void**)&v,        g_v);
    cudaGetSymbolAddress((void**)&ctx,      g_ctx);
    cudaGetSymbolAddress((void**)&res,      g_res);
    cudaGetSymbolAddress((void**)&xr,       g_xr);
    cudaGetSymbolAddress((void**)&wr,       g_wr);
    cudaGetSymbolAddress((void**)&rowm,     g_rowm);
    cudaGetSymbolAddress((void**)&rowl,     g_rowl);
    cudaGetSymbolAddress((void**)&attn_scr, g_attn_scratch);

    const size_t OUT_E  = (size_t)BB * SS * DIMM;
    const size_t ATTN_E = (size_t)BB * HH * SS * SS;
    float* attn = ((size_t)out_size >= OUT_E + ATTN_E) ? (out + OUT_E)
                                                       : attn_scr;

    cudaFuncSetAttribute(qkv_gemm,
                         cudaFuncAttributeMaxDynamicSharedMemorySize, GEMM_SMEM);
    cudaFuncSetAttribute(o_gemm,
                         cudaFuncAttributeMaxDynamicSharedMemorySize, GEMM_SMEM);
    cudaFuncSetAttribute(scores_kernel,
                         cudaFuncAttributeMaxDynamicSharedMemorySize, SC_SMEM);
    cudaFuncSetAttribute(pv_kernel,
                         cudaFuncAttributeMaxDynamicSharedMemorySize, PV_SMEM);

    const int M = BB * SS;  // 4096

    preround_kernel<<<dim3(1024, 5), 256>>>(x, xr, Wq, Wk, Wv, Wo, wr);

    qkv_gemm<<<dim3(DIMM / 128, M / 128, 3), 256, GEMM_SMEM>>>(
        xr, wr, bq, q, bk, k, bv, v);

    scores_kernel<<<dim3(8, 8, BB * HH), 256, SC_SMEM>>>(q, k, rel, mask, attn);

    stats_kernel<<<BB * HH * SS, 256>>>(attn, rowm, rowl);

    pv_kernel<<<dim3(16, BB * HH), 256, PV_SMEM>>>(attn, v, rowm, rowl, ctx);

    o_gemm<<<dim3(DIMM / 128, M / 128), 256, GEMM_SMEM>>>(
        ctx, wr + (size_t)3 * DIMM * DIMM, bo, x, res);

    ln_kernel<<<M, 256>>>(res, gamma, beta, out);
}

// round 6
// speedup vs baseline: 1.0400x; 1.0400x over previous
#include <cuda_runtime.h>
#include <math.h>
#include <stdint.h>

#define BB   4
#define SS   1024
#define HH   16
#define SZ   64
#define DIMM 1024
#define NINF -10000.0f

// ---------------- scratch (device globals; no runtime allocation) ----------
__device__ float g_q[BB * SS * DIMM];
__device__ float g_k[BB * SS * DIMM];
__device__ float g_v[BB * SS * DIMM];
__device__ float g_ctx[BB * SS * DIMM];
__device__ float g_res[BB * SS * DIMM];
__device__ float g_xr[BB * SS * DIMM];        // tf32-rounded x
__device__ float g_wr[4][DIMM * DIMM];        // tf32-rounded Wq,Wk,Wv,Wo
__device__ float g_pm[BB * HH * 8 * SS];      // per-(row, t-tile) partial max
__device__ float g_pl[BB * HH * 8 * SS];      // per-(row, t-tile) partial sumexp
__device__ float g_rowm[BB * HH * SS];        // per-row max
__device__ float g_rowl[BB * HH * SS];        // per-row 1/sum
__device__ float g_attn_scratch[BB * HH * SS * SS];

// ---------------- small PTX helpers ----------------------------------------
__device__ __forceinline__ uint32_t f2tf(float f) {
    uint32_t r;
    asm volatile("cvt.rna.tf32.f32 %0, %1;" : "=r"(r) : "f"(f));
    return r;
}
__device__ __forceinline__ float tf32r(float f) { return __uint_as_float(f2tf(f)); }

__device__ __forceinline__ void mma_tf32(float c[4], const uint32_t a[4],
                                         const uint32_t b[2]) {
    asm volatile(
        "mma.sync.aligned.m16n8k8.row.col.f32.tf32.tf32.f32 "
        "{%0,%1,%2,%3}, {%4,%5,%6,%7}, {%8,%9}, {%0,%1,%2,%3};"
        : "+f"(c[0]), "+f"(c[1]), "+f"(c[2]), "+f"(c[3])
        : "r"(a[0]), "r"(a[1]), "r"(a[2]), "r"(a[3]), "r"(b[0]), "r"(b[1]));
}
__device__ __forceinline__ void cp16(uint32_t s, const void* g) {
    asm volatile("cp.async.cg.shared.global [%0], [%1], 16;" :: "r"(s), "l"(g));
}
#define CP_COMMIT() asm volatile("cp.async.commit_group;")
#define CP_WAIT1()  asm volatile("cp.async.wait_group 1;")
#define CP_WAIT0()  asm volatile("cp.async.wait_group 0;")

// ---------------------------------------------------------------------------
// preround: tf32-round x and the four weight matrices (once)
// ---------------------------------------------------------------------------
__global__ __launch_bounds__(256) void preround_kernel(
    const float* __restrict__ x, float* __restrict__ xr,
    const float* __restrict__ Wq, const float* __restrict__ Wk,
    const float* __restrict__ Wv, const float* __restrict__ Wo,
    float* __restrict__ wr)
{
    const int y = blockIdx.y;
    const float* in;
    float* out;
    int n4;
    if (y == 0) { in = x;  out = xr;                n4 = BB * SS * DIMM / 4; }
    else {
        in = (y == 1) ? Wq : (y == 2) ? Wk : (y == 3) ? Wv : Wo;
        out = wr + (size_t)(y - 1) * DIMM * DIMM;   n4 = DIMM * DIMM / 4;
    }
    for (int i = blockIdx.x * 256 + threadIdx.x; i < n4; i += 1024 * 256) {
        float4 v = ((const float4*)in)[i];
        v.x = tf32r(v.x); v.y = tf32r(v.y); v.z = tf32r(v.z); v.w = tf32r(v.w);
        ((float4*)out)[i] = v;
    }
}

// ---------------------------------------------------------------------------
// TF32 GEMM core (operands PRE-ROUNDED): 128x128x32 tiles, 256 thr, 8 warps
// ---------------------------------------------------------------------------
#define A_STR 36
#define W_STR 136
#define A_TILE (128 * A_STR)
#define W_TILE (32 * W_STR)
#define GEMM_SMEM ((A_TILE + W_TILE) * 2 * 4)  // 71680 B

struct GemmCore {
    const float* A; const float* W; int N; int K; int bm; int bn;
    float* smem;
    float acc[4][4][4];

    __device__ __forceinline__ void run(int tid) {
        float* As[2] = { smem, smem + A_TILE + W_TILE };
        float* Ws[2] = { smem + A_TILE, smem + A_TILE + W_TILE + A_TILE };
        const int lane = tid & 31, warp = tid >> 5;
        const int wm = warp >> 2, wn = warp & 3;
        const int r = lane >> 2, cl = lane & 3;

#pragma unroll
        for (int mt = 0; mt < 4; mt++)
#pragma unroll
            for (int nt = 0; nt < 4; nt++)
#pragma unroll
                for (int i = 0; i < 4; i++) acc[mt][nt][i] = 0.f;

        auto load_stage = [&](int b, int kt) {
            float* as = As[b];
            float* ws = Ws[b];
#pragma unroll
            for (int j = 0; j < 4; j++) {
                const int idx = tid + j * 256;
                const int ar = idx >> 3, ac = (idx & 7) * 4;
                cp16((uint32_t)__cvta_generic_to_shared(as + ar * A_STR + ac),
                     A + (size_t)(bm + ar) * K + kt + ac);
                const int wk = idx >> 5, wc = (idx & 31) * 4;
                cp16((uint32_t)__cvta_generic_to_shared(ws + wk * W_STR + wc),
                     W + (size_t)(kt + wk) * N + bn + wc);
            }
        };

        load_stage(0, 0);
        CP_COMMIT();

        const int T = K / 32;
        int buf = 0;
        for (int t = 0; t < T; t++) {
            if (t + 1 < T) { load_stage(buf ^ 1, (t + 1) * 32); CP_COMMIT(); CP_WAIT1(); }
            else           { CP_WAIT0(); }
            __syncthreads();
            const float* as = As[buf];
            const float* ws = Ws[buf];
#pragma unroll
            for (int ks = 0; ks < 4; ks++) {
                uint32_t af[4][4];
#pragma unroll
                for (int mt = 0; mt < 4; mt++) {
                    const float* p = as + (wm * 64 + mt * 16 + r) * A_STR + ks * 8 + cl;
                    af[mt][0] = __float_as_uint(p[0]);
                    af[mt][1] = __float_as_uint(p[8 * A_STR]);
                    af[mt][2] = __float_as_uint(p[4]);
                    af[mt][3] = __float_as_uint(p[8 * A_STR + 4]);
                }
                uint32_t bf[4][2];
#pragma unroll
                for (int nt = 0; nt < 4; nt++) {
                    const float* p = ws + (ks * 8 + cl) * W_STR + wn * 32 + nt * 8 + r;
                    bf[nt][0] = __float_as_uint(p[0]);
                    bf[nt][1] = __float_as_uint(p[4 * W_STR]);
                }
#pragma unroll
                for (int mt = 0; mt < 4; mt++)
#pragma unroll
                    for (int nt = 0; nt < 4; nt++)
                        mma_tf32(acc[mt][nt], af[mt], bf[nt]);
            }
            __syncthreads();
            buf ^= 1;
        }
    }
};

// QKV: outputs tf32-rounded q/k/v
__global__ __launch_bounds__(256, 2) void qkv_gemm(
    const float* __restrict__ xr, const float* __restrict__ wr,
    const float* __restrict__ bq, float* __restrict__ qo,
    const float* __restrict__ bk, float* __restrict__ ko,
    const float* __restrict__ bv, float* __restrict__ vo)
{
    extern __shared__ float sm[];
    const float* W = wr + (size_t)blockIdx.z * DIMM * DIMM;
    const float* bias = (blockIdx.z == 0) ? bq : (blockIdx.z == 1) ? bk : bv;
    float* C = (blockIdx.z == 0) ? qo : (blockIdx.z == 1) ? ko : vo;

    GemmCore g;
    g.A = xr; g.W = W; g.N = DIMM; g.K = DIMM;
    g.bm = blockIdx.y * 128; g.bn = blockIdx.x * 128; g.smem = sm;
    g.run(threadIdx.x);

    const int lane = threadIdx.x & 31, warp = threadIdx.x >> 5;
    const int wm = warp >> 2, wn = warp & 3;
    const int r = lane >> 2, cl = lane & 3;
#pragma unroll
    for (int mt = 0; mt < 4; mt++) {
        const int row0 = g.bm + wm * 64 + mt * 16 + r;
#pragma unroll
        for (int nt = 0; nt < 4; nt++) {
            const int col = g.bn + wn * 32 + nt * 8 + 2 * cl;
            const float b0 = bias[col], b1 = bias[col + 1];
            *(float2*)(C + (size_t)row0 * DIMM + col) =
                make_float2(tf32r(g.acc[mt][nt][0] + b0), tf32r(g.acc[mt][nt][1] + b1));
            *(float2*)(C + (size_t)(row0 + 8) * DIMM + col) =
                make_float2(tf32r(g.acc[mt][nt][2] + b0), tf32r(g.acc[mt][nt][3] + b1));
        }
    }
}

// O projection with residual (residual = ORIGINAL x; output full f32 for LN)
__global__ __launch_bounds__(256, 2) void o_gemm(
    const float* __restrict__ A, const float* __restrict__ W,
    const float* __restrict__ bias, const float* __restrict__ resid,
    float* __restrict__ C)
{
    extern __shared__ float sm[];
    GemmCore g;
    g.A = A; g.W = W; g.N = DIMM; g.K = DIMM;
    g.bm = blockIdx.y * 128; g.bn = blockIdx.x * 128; g.smem = sm;
    g.run(threadIdx.x);

    const int lane = threadIdx.x & 31, warp = threadIdx.x >> 5;
    const int wm = warp >> 2, wn = warp & 3;
    const int r = lane >> 2, cl = lane & 3;
#pragma unroll
    for (int mt = 0; mt < 4; mt++) {
        const int row0 = g.bm + wm * 64 + mt * 16 + r;
#pragma unroll
        for (int nt = 0; nt < 4; nt++) {
            const int col = g.bn + wn * 32 + nt * 8 + 2 * cl;
            const float b0 = bias[col], b1 = bias[col + 1];
            float v00 = g.acc[mt][nt][0] + b0 + resid[(size_t)row0 * DIMM + col];
            float v01 = g.acc[mt][nt][1] + b1 + resid[(size_t)row0 * DIMM + col + 1];
            float v10 = g.acc[mt][nt][2] + b0 + resid[(size_t)(row0 + 8) * DIMM + col];
            float v11 = g.acc[mt][nt][3] + b1 + resid[(size_t)(row0 + 8) * DIMM + col + 1];
            *(float2*)(C + (size_t)row0 * DIMM + col)       = make_float2(v00, v01);
            *(float2*)(C + (size_t)(row0 + 8) * DIMM + col) = make_float2(v10, v11);
        }
    }
}

// ---------------------------------------------------------------------------
// scores_kernel: writes RAW s = Q.K^T/8 + rel + mask*NINF  AND per-(row,tile)
// partial softmax stats (max, sumexp). 128x128 tile. grid (8 t, 8 s, 64 bh)
// ---------------------------------------------------------------------------
#define SC_STR 68
#define SC_SMEM ((2 * 128 * SC_STR + 2 * 4 * 128) * 4)   // 73728 B

__global__ __launch_bounds__(256, 2) void scores_kernel(
    const float* __restrict__ q, const float* __restrict__ k,
    const float* __restrict__ rel, const int* __restrict__ mask,
    float* __restrict__ sraw, float* __restrict__ pm, float* __restrict__ pl)
{
    extern __shared__ float sm[];
    float* sQ = sm;
    float* sK = sm + 128 * SC_STR;
    float* redm = sm + 2 * 128 * SC_STR;   // [4][128]
    float* redl = redm + 4 * 128;          // [4][128]

    const int tid = threadIdx.x;
    const int lane = tid & 31, warp = tid >> 5;
    const int wm = warp >> 2, wn = warp & 3;
    const int r = lane >> 2, cl = lane & 3;

    const int bh = blockIdx.z;
    const int b = bh >> 4, h = bh & 15;
    const int s0 = blockIdx.y * 128;
    const int t0 = blockIdx.x * 128;

    const float* qb = q + ((size_t)b * SS + s0) * DIMM + h * SZ;
    const float* kb = k + ((size_t)b * SS + t0) * DIMM + h * SZ;
    const float* relb = rel + ((size_t)h * SS + s0) * SS + t0;
    const int* maskb = mask + b * SS + t0;

    for (int idx = tid; idx < 128 * 16; idx += 256) {
        const int rr = idx >> 4, c4 = (idx & 15) * 4;
        float4 qv = *(const float4*)(qb + (size_t)rr * DIMM + c4);
        qv.x *= 0.125f; qv.y *= 0.125f; qv.z *= 0.125f; qv.w *= 0.125f;
        *(float4*)&sQ[rr * SC_STR + c4] = qv;
        *(float4*)&sK[rr * SC_STR + c4] = *(const float4*)(kb + (size_t)rr * DIMM + c4);
    }
    __syncthreads();

    float acc[4][4][4];
#pragma unroll
    for (int mt = 0; mt < 4; mt++)
#pragma unroll
        for (int nt = 0; nt < 4; nt++)
#pragma unroll
            for (int i = 0; i < 4; i++) acc[mt][nt][i] = 0.f;

#pragma unroll
    for (int ks = 0; ks < 8; ks++) {
        uint32_t af[4][4];
#pragma unroll
        for (int mt = 0; mt < 4; mt++) {
            const float* p = sQ + (wm * 64 + mt * 16 + r) * SC_STR + ks * 8 + cl;
            af[mt][0] = __float_as_uint(p[0]);
            af[mt][1] = __float_as_uint(p[8 * SC_STR]);
            af[mt][2] = __float_as_uint(p[4]);
            af[mt][3] = __float_as_uint(p[8 * SC_STR + 4]);
        }
        uint32_t bf[4][2];
#pragma unroll
        for (int nt = 0; nt < 4; nt++) {
            const float* p = sK + (wn * 32 + nt * 8 + r) * SC_STR + ks * 8 + cl;
            bf[nt][0] = __float_as_uint(p[0]);
            bf[nt][1] = __float_as_uint(p[4]);
        }
#pragma unroll
        for (int mt = 0; mt < 4; mt++)
#pragma unroll
            for (int nt = 0; nt < 4; nt++)
                mma_tf32(acc[mt][nt], af[mt], bf[nt]);
    }

    // ---- add rel+mask in regs, write raw scores ----
    float* ob = sraw + (((size_t)bh) * SS + s0) * SS + t0;
#pragma unroll
    for (int mt = 0; mt < 4; mt++) {
        const int row0 = wm * 64 + mt * 16 + r;
#pragma unroll
        for (int nt = 0; nt < 4; nt++) {
            const int col = wn * 32 + nt * 8 + 2 * cl;
            const int2 mk = *(const int2*)(maskb + col);
            const float m0 = (float)mk.x * NINF, m1 = (float)mk.y * NINF;
            const float2 rl0 = *(const float2*)(relb + (size_t)row0 * SS + col);
            const float2 rl1 = *(const float2*)(relb + (size_t)(row0 + 8) * SS + col);
            acc[mt][nt][0] += rl0.x + m0;
            acc[mt][nt][1] += rl0.y + m1;
            acc[mt][nt][2] += rl1.x + m0;
            acc[mt][nt][3] += rl1.y + m1;
            *(float2*)(ob + (size_t)row0 * SS + col) =
                make_float2(acc[mt][nt][0], acc[mt][nt][1]);
            *(float2*)(ob + (size_t)(row0 + 8) * SS + col) =
                make_float2(acc[mt][nt][2], acc[mt][nt][3]);
        }
    }

    // ---- per-row tile max ----
    float lm[4][2];
#pragma unroll
    for (int mt = 0; mt < 4; mt++) {
        lm[mt][0] = -1e30f; lm[mt][1] = -1e30f;
#pragma unroll
        for (int nt = 0; nt < 4; nt++) {
            lm[mt][0] = fmaxf(lm[mt][0], fmaxf(acc[mt][nt][0], acc[mt][nt][1]));
            lm[mt][1] = fmaxf(lm[mt][1], fmaxf(acc[mt][nt][2], acc[mt][nt][3]));
        }
#pragma unroll
        for (int hf = 0; hf < 2; hf++) {
            lm[mt][hf] = fmaxf(lm[mt][hf], __shfl_xor_sync(~0u, lm[mt][hf], 1));
            lm[mt][hf] = fmaxf(lm[mt][hf], __shfl_xor_sync(~0u, lm[mt][hf], 2));
        }
        if (cl == 0) {
            const int lr = wm * 64 + mt * 16 + r;
            redm[wn * 128 + lr]     = lm[mt][0];
            redm[wn * 128 + lr + 8] = lm[mt][1];
        }
    }
    __syncthreads();

    // ---- per-row tile sumexp ----
    float rm[4][2], ls[4][2];
#pragma unroll
    for (int mt = 0; mt < 4; mt++) {
        const int lr = wm * 64 + mt * 16 + r;
#pragma unroll
        for (int hf = 0; hf < 2; hf++) {
            const int rr = lr + hf * 8;
            float m = fmaxf(fmaxf(redm[rr], redm[128 + rr]),
                            fmaxf(redm[256 + rr], redm[384 + rr]));
            rm[mt][hf] = m;
            float s = 0.f;
#pragma unroll
            for (int nt = 0; nt < 4; nt++) {
                s += __expf(acc[mt][nt][2 * hf]     - m);
                s += __expf(acc[mt][nt][2 * hf + 1] - m);
            }
            s += __shfl_xor_sync(~0u, s, 1);
            s += __shfl_xor_sync(~0u, s, 2);
            ls[mt][hf] = s;
        }
        if (cl == 0) {
            const int lr2 = wm * 64 + mt * 16 + r;
            redl[wn * 128 + lr2]     = ls[mt][0];
            redl[wn * 128 + lr2 + 8] = ls[mt][1];
        }
    }
    __syncthreads();

    // ---- one writer per row: combine over wn, write partials ----
    if (wn == 0 && cl == 0) {
        const size_t base = ((size_t)bh * 8 + blockIdx.x) * SS + s0;
#pragma unroll
        for (int mt = 0; mt < 4; mt++) {
#pragma unroll
            for (int hf = 0; hf < 2; hf++) {
                const int rr = wm * 64 + mt * 16 + r + hf * 8;
                const float l = redl[rr] + redl[128 + rr] +
                                redl[256 + rr] + redl[384 + rr];
                pm[base + rr] = rm[mt][hf];
                pl[base + rr] = l;
            }
        }
    }
}

// ---------------------------------------------------------------------------
// combine_kernel: rowm = max_t pm, rowl = 1/sum_t(pl*exp(pm-m)). 4 MB read.
// ---------------------------------------------------------------------------
__global__ __launch_bounds__(256) void combine_kernel(
    const float* __restrict__ pm, const float* __restrict__ pl,
    float* __restrict__ rowm, float* __restrict__ rowl)
{
    const int gid = blockIdx.x * 256 + threadIdx.x;   // 65536 rows
    const int bh = gid >> 10, s = gid & 1023;
    const float* pmb = pm + (size_t)bh * 8 * SS + s;
    const float* plb = pl + (size_t)bh * 8 * SS + s;
    float m = -1e30f;
#pragma unroll
    for (int t = 0; t < 8; t++) m = fmaxf(m, pmb[t * SS]);
    float l = 0.f;
#pragma unroll
    for (int t = 0; t < 8; t++) l += plb[t * SS] * __expf(pmb[t * SS] - m);
    rowm[gid] = m;
    rowl[gid] = 1.f / l;
}

// ---------------------------------------------------------------------------
// apply_kernel: in-place p = exp(s - m) * linv. One block per row.
// ---------------------------------------------------------------------------
__global__ __launch_bounds__(256) void apply_kernel(
    float* __restrict__ attn, const float* __restrict__ rowm,
    const float* __restrict__ rowl)
{
    const int row = blockIdx.x;
    const float m = rowm[row], linv = rowl[row];
    float4* p = (float4*)(attn + (size_t)row * SS);
    float4 v = p[threadIdx.x];
    v.x = __expf(v.x - m) * linv;
    v.y = __expf(v.y - m) * linv;
    v.z = __expf(v.z - m) * linv;
    v.w = __expf(v.w - m) * linv;
    p[threadIdx.x] = v;
}

// ---------------------------------------------------------------------------
// pv_kernel (R4 version): ctx = P @ V from normalized attn.
// Tile 128(M) x 64(N), K chunks of 64 double-buffered. grid (8 m-tiles, 64 bh)
// ---------------------------------------------------------------------------
#define P_STR 68
#define V_STR 72
#define PV_CHUNK_FLOATS (128 * P_STR + 64 * V_STR)
#define PV_SMEM (2 * PV_CHUNK_FLOATS * 4)   // 106496 B

__global__ __launch_bounds__(256, 1) void pv_kernel(
    const float* __restrict__ attn, const float* __restrict__ v,
    float* __restrict__ ctx)
{
    extern __shared__ float sm[];
    float* sP[2] = { sm, sm + PV_CHUNK_FLOATS };
    float* sV[2] = { sm + 128 * P_STR, sm + PV_CHUNK_FLOATS + 128 * P_STR };

    const int tid = threadIdx.x;
    const int lane = tid & 31, warp = tid >> 5;
    const int wm = warp >> 2, wn = warp & 3;
    const int r = lane >> 2, cl = lane & 3;

    const int bh = blockIdx.y;
    const int b = bh >> 4, h = bh & 15;
    const int s0 = blockIdx.x * 128;

    const float* pb = attn + (((size_t)bh) * SS + s0) * SS;
    const float* vb = v + (size_t)b * SS * DIMM + h * SZ;

    auto load_stage = [&](int buf, int t0) {
#pragma unroll
        for (int j = 0; j < 8; j++) {
            const int idx = tid + j * 256;
            const int pr = idx >> 4, c4 = (idx & 15) * 4;
            cp16((uint32_t)__cvta_generic_to_shared(sP[buf] + pr * P_STR + c4),
                 pb + (size_t)pr * SS + t0 + c4);
        }
#pragma unroll
        for (int j = 0; j < 4; j++) {
            const int idx = tid + j * 256;
            const int vr = idx >> 4, c4 = (idx & 15) * 4;
            cp16((uint32_t)__cvta_generic_to_shared(sV[buf] + vr * V_STR + c4),
                 vb + (size_t)(t0 + vr) * DIMM + c4);
        }
    };

    float acc[4][2][4];
#pragma unroll
    for (int mt = 0; mt < 4; mt++)
#pragma unroll
        for (int nt = 0; nt < 2; nt++)
#pragma unroll
            for (int i = 0; i < 4; i++) acc[mt][nt][i] = 0.f;

    load_stage(0, 0);
    CP_COMMIT();

    int buf = 0;
    for (int t = 0; t < 16; t++) {
        if (t + 1 < 16) { load_stage(buf ^ 1, (t + 1) * 64); CP_COMMIT(); CP_WAIT1(); }
        else            { CP_WAIT0(); }
        __syncthreads();
        const float* ps = sP[buf];
        const float* vs = sV[buf];
#pragma unroll
        for (int ks = 0; ks < 8; ks++) {
            uint32_t af[4][4];
#pragma unroll
            for (int mt = 0; mt < 4; mt++) {
                const float* p = ps + (wm * 64 + mt * 16 + r) * P_STR + ks * 8 + cl;
                af[mt][0] = f2tf(p[0]);
                af[mt][1] = f2tf(p[8 * P_STR]);
                af[mt][2] = f2tf(p[4]);
                af[mt][3] = f2tf(p[8 * P_STR + 4]);
            }
            uint32_t bf[2][2];
#pragma unroll
            for (int nt = 0; nt < 2; nt++) {
                const float* p = vs + (ks * 8 + cl) * V_STR + wn * 16 + nt * 8 + r;
                bf[nt][0] = __float_as_uint(p[0]);
                bf[nt][1] = __float_as_uint(p[4 * V_STR]);
            }
#pragma unroll
            for (int mt = 0; mt < 4; mt++)
#pragma unroll
                for (int nt = 0; nt < 2; nt++)
                    mma_tf32(acc[mt][nt], af[mt], bf[nt]);
        }
        __syncthreads();
        buf ^= 1;
    }

#pragma unroll
    for (int mt = 0; mt < 4; mt++) {
        const int row0 = s0 + wm * 64 + mt * 16 + r;
#pragma unroll
        for (int nt = 0; nt < 2; nt++) {
            const int col = h * SZ + wn * 16 + nt * 8 + 2 * cl;
            *(float2*)(ctx + ((size_t)b * SS + row0) * DIMM + col) =
                make_float2(tf32r(acc[mt][nt][0]), tf32r(acc[mt][nt][1]));
            *(float2*)(ctx + ((size_t)b * SS + row0 + 8) * DIMM + col) =
                make_float2(tf32r(acc[mt][nt][2]), tf32r(acc[mt][nt][3]));
        }
    }
}

// ---------------------------------------------------------------------------
// LayerNorm
// ---------------------------------------------------------------------------
__global__ __launch_bounds__(256) void ln_kernel(
    const float* __restrict__ res, const float* __restrict__ gamma,
    const float* __restrict__ beta, float* __restrict__ out)
{
    __shared__ float sred[2][8];
    const int row = blockIdx.x;
    const int tid = threadIdx.x;
    const float4 vv = ((const float4*)(res + (size_t)row * DIMM))[tid];
    float s  = vv.x + vv.y + vv.z + vv.w;
    float ss = vv.x * vv.x + vv.y * vv.y + vv.z * vv.z + vv.w * vv.w;
#pragma unroll
    for (int o = 16; o >= 1; o >>= 1) {
        s  += __shfl_xor_sync(~0u, s, o);
        ss += __shfl_xor_sync(~0u, ss, o);
    }
    if ((tid & 31) == 0) { sred[0][tid >> 5] = s; sred[1][tid >> 5] = ss; }
    __syncthreads();
    float ts = 0.f, tss = 0.f;
#pragma unroll
    for (int i = 0; i < 8; i++) { ts += sred[0][i]; tss += sred[1][i]; }
    const float mu   = ts * (1.f / DIMM);
    const float var  = tss * (1.f / DIMM) - mu * mu;
    const float rstd = rsqrtf(var + 1e-6f);
    const float4 g  = ((const float4*)gamma)[tid];
    const float4 be = ((const float4*)beta)[tid];
    float4 o4;
    o4.x = (vv.x - mu) * rstd * g.x + be.x;
    o4.y = (vv.y - mu) * rstd * g.y + be.y;
    o4.z = (vv.z - mu) * rstd * g.z + be.z;
    o4.w = (vv.w - mu) * rstd * g.w + be.w;
    ((float4*)(out + (size_t)row * DIMM))[tid] = o4;
}

// ---------------------------------------------------------------------------
extern "C" void kernel_launch(void* const* d_in, const int* in_sizes, int n_in,
                              void* d_out, int out_size)
{
    const float* x     = (const float*)d_in[0];
    const int*   mask  = (const int*)d_in[1];
    const float* rel   = (const float*)d_in[2];
    const float* Wq    = (const float*)d_in[3];
    const float* bq    = (const float*)d_in[4];
    const float* Wk    = (const float*)d_in[5];
    const float* bk    = (const float*)d_in[6];
    const float* Wv    = (const float*)d_in[7];
    const float* bv    = (const float*)d_in[8];
    const float* Wo    = (const float*)d_in[9];
    const float* bo    = (const float*)d_in[10];
    const float* gamma = (const float*)d_in[11];
    const float* beta  = (const float*)d_in[12];
    float* out = (float*)d_out;

    float *q, *k, *v, *ctx, *res, *xr, *wr, *pm, *pl, *rowm, *rowl, *attn_scr;
    cudaGetSymbolAddress((void**)&q,        g_q);
    cudaGetSymbolAddress((void**)&k,        g_k);
    cudaGetSymbolAddress((void**)&v,        g_v);
    cudaGetSymbolAddress((void**)&ctx,      g_ctx);
    cudaGetSymbolAddress((void**)&res,      g_res);
    cudaGetSymbolAddress((void**)&xr,       g_xr);
    cudaGetSymbolAddress((void**)&wr,       g_wr);
    cudaGetSymbolAddress((void**)&pm,       g_pm);
    cudaGetSymbolAddress((void**)&pl,       g_pl);
    cudaGetSymbolAddress((void**)&rowm,     g_rowm);
    cudaGetSymbolAddress((void**)&rowl,     g_rowl);
    cudaGetSymbolAddress((void**)&attn_scr, g_attn_scratch);

    const size_t OUT_E  = (size_t)BB * SS * DIMM;
    const size_t ATTN_E = (size_t)BB * HH * SS * SS;
    float* attn = ((size_t)out_size >= OUT_E + ATTN_E) ? (out + OUT_E)
                                                       : attn_scr;

    cudaFuncSetAttribute(qkv_gemm,
                         cudaFuncAttributeMaxDynamicSharedMemorySize, GEMM_SMEM);
    cudaFuncSetAttribute(o_gemm,
                         cudaFuncAttributeMaxDynamicSharedMemorySize, GEMM_SMEM);
    cudaFuncSetAttribute(scores_kernel,
                         cudaFuncAttributeMaxDynamicSharedMemorySize, SC_SMEM);
    cudaFuncSetAttribute(pv_kernel,
                         cudaFuncAttributeMaxDynamicSharedMemorySize, PV_SMEM);

    const int M = BB * SS;  // 4096

    preround_kernel<<<dim3(1024, 5), 256>>>(x, xr, Wq, Wk, Wv, Wo, wr);

    qkv_gemm<<<dim3(DIMM / 128, M / 128, 3), 256, GEMM_SMEM>>>(
        xr, wr, bq, q, bk, k, bv, v);

    scores_kernel<<<dim3(8, 8, BB * HH), 256, SC_SMEM>>>(
        q, k, rel, mask, attn, pm, pl);

    combine_kernel<<<BB * HH * SS / 256, 256>>>(pm, pl, rowm, rowl);

    apply_kernel<<<BB * HH * SS, 256>>>(attn, rowm, rowl);

    pv_kernel<<<dim3(8, BB * HH), 256, PV_SMEM>>>(attn, v, ctx);

    o_gemm<<<dim3(DIMM / 128, M / 128), 256, GEMM_SMEM>>>(
        ctx, wr + (size_t)3 * DIMM * DIMM, bo, x, res);

    ln_kernel<<<M, 256>>>(res, gamma, beta, out);
}